// round 1
// baseline (speedup 1.0000x reference)
#include <cuda_runtime.h>
#include <cuda_bf16.h>

// Problem constants
#define BB 64
#define HH 1024
#define II 512
#define MIN_TAU 1e-3f

// Fused: input GEMM row-dot + gumbel-softmax-weighted hidden mix + tanh.
// One warp per (b, o) output element. Single pass over the 268MB gumbel tensor.
// Softmax computed WITHOUT max-subtraction: logits are bounded (<~18.5 from
// the Gumbel construction with u in [1e-8, 1-1e-8]), so exp() cannot overflow
// and fp32 sums stay well-conditioned (sum <= ~1e11).
__global__ __launch_bounds__(256, 8) void reservoir_cell_kernel(
    const float* __restrict__ x_t,        // (B, I)
    const float* __restrict__ h_prev,     // (B, H)
    const float* __restrict__ W_ih,       // (H, I)
    const float* __restrict__ b_ih,       // (H,)
    const float* __restrict__ W_hh,       // (H, H)
    const float* __restrict__ temperature,// scalar
    const float* __restrict__ gumbel,     // (B, H, H)
    float* __restrict__ out)              // (B, H)
{
    const int warp = (blockIdx.x * blockDim.x + threadIdx.x) >> 5;
    const int lane = threadIdx.x & 31;
    const int b = warp >> 10;      // warp / H
    const int o = warp & (HH - 1); // warp % H

    const float tau = fmaxf(temperature[0], MIN_TAU);
    const float inv_tau = 1.0f / tau;

    // ---- input contribution: dot(x_t[b, :], W_ih[o, :]) over I = 512 ----
    // 512 / 32 lanes = 16 floats = 4 x float4 per lane. x_t and W_ih are
    // L2-resident (128KB / 2MB), broadcast-reused across the grid.
    const float4* __restrict__ xr = reinterpret_cast<const float4*>(x_t + (size_t)b * II);
    const float4* __restrict__ wi = reinterpret_cast<const float4*>(W_ih + (size_t)o * II);
    float ic = 0.0f;
#pragma unroll
    for (int k = 0; k < 4; ++k) {
        const float4 xv = xr[lane + 32 * k];
        const float4 wv = wi[lane + 32 * k];
        ic = fmaf(xv.x, wv.x, ic);
        ic = fmaf(xv.y, wv.y, ic);
        ic = fmaf(xv.z, wv.z, ic);
        ic = fmaf(xv.w, wv.w, ic);
    }

    // ---- gumbel-softmax weighted mix over h = 1024 ----
    // 1024 / 32 lanes = 32 floats = 8 x float4 per lane. Coalesced 128B
    // transactions; gumbel row is the streaming (DRAM) term, W_hh row and
    // h_prev row are L2 hits (4MB / 256KB, heavily reused).
    const float4* __restrict__ gr =
        reinterpret_cast<const float4*>(gumbel + (((size_t)b * HH + o) * HH));
    const float4* __restrict__ wh =
        reinterpret_cast<const float4*>(W_hh + (size_t)o * HH);
    const float4* __restrict__ hr =
        reinterpret_cast<const float4*>(h_prev + (size_t)b * HH);

    float s = 0.0f;  // softmax denominator
    float t = 0.0f;  // softmax-weighted h_prev numerator
#pragma unroll
    for (int k = 0; k < 8; ++k) {
        const int idx = lane + 32 * k;
        const float4 g = gr[idx];
        const float4 w = wh[idx];
        const float4 h = hr[idx];
        float e;
        e = __expf(fmaf(w.x, inv_tau, g.x)); s += e; t = fmaf(e, h.x, t);
        e = __expf(fmaf(w.y, inv_tau, g.y)); s += e; t = fmaf(e, h.y, t);
        e = __expf(fmaf(w.z, inv_tau, g.z)); s += e; t = fmaf(e, h.z, t);
        e = __expf(fmaf(w.w, inv_tau, g.w)); s += e; t = fmaf(e, h.w, t);
    }

    // ---- warp reductions ----
#pragma unroll
    for (int off = 16; off > 0; off >>= 1) {
        s  += __shfl_xor_sync(0xffffffffu, s,  off);
        t  += __shfl_xor_sync(0xffffffffu, t,  off);
        ic += __shfl_xor_sync(0xffffffffu, ic, off);
    }

    if (lane == 0) {
        out[(size_t)b * HH + o] = tanhf(ic + b_ih[o] + t / s);
    }
}

extern "C" void kernel_launch(void* const* d_in, const int* in_sizes, int n_in,
                              void* d_out, int out_size) {
    // metadata order: x_t, h_prev, W_ih, b_ih, W_hh, temperature, gumbel_noise
    const float* x_t   = (const float*)d_in[0];
    const float* h_prev= (const float*)d_in[1];
    const float* W_ih  = (const float*)d_in[2];
    const float* b_ih  = (const float*)d_in[3];
    const float* W_hh  = (const float*)d_in[4];
    const float* temp  = (const float*)d_in[5];
    const float* gum   = (const float*)d_in[6];
    float* out = (float*)d_out;

    // B*H = 65536 warps; 8 warps (256 threads) per block -> 8192 blocks
    const int total_warps = BB * HH;
    const int warps_per_block = 8;
    dim3 grid(total_warps / warps_per_block);
    dim3 block(warps_per_block * 32);
    reservoir_cell_kernel<<<grid, block>>>(x_t, h_prev, W_ih, b_ih, W_hh, temp, gum, out);
}